// round 2
// baseline (speedup 1.0000x reference)
#include <cuda_runtime.h>

#define Wd   1024
#define Hd   1024
#define Bd   16
#define RPB  8
#define NBLK ((Bd * Hd) / RPB)   // 2048 blocks
#define TPB  256                  // 256 threads * 4 floats = 1024 = one row

__device__ float g_partial[NBLK];

__device__ __forceinline__ float4 hmax4(float4 t, float l, float r) {
    float4 h;
    h.x = fmaxf(l,   fmaxf(t.x, t.y));
    h.y = fmaxf(t.x, fmaxf(t.y, t.z));
    h.z = fmaxf(t.y, fmaxf(t.z, t.w));
    h.w = fmaxf(t.z, fmaxf(t.w, r));
    return h;
}

__global__ __launch_bounds__(TPB)
void bce_partial_kernel(const float* __restrict__ pred,
                        const float* __restrict__ tgt) {
    const int r0 = blockIdx.x * RPB;       // first global row for this block
    const int x4 = threadIdx.x * 4;        // column of this thread's float4
    const bool has_left  = (x4 > 0);
    const bool has_right = (x4 + 4 < Wd);
    const int y0 = r0 & (Hd - 1);          // row within image (RPB divides Hd)

    // Load one target row: returns horizontal 3-max per lane, outputs raw float4.
    auto load_row = [&](int r, float4& t4) -> float4 {
        const float* p = tgt + (size_t)r * Wd + x4;
        t4 = *reinterpret_cast<const float4*>(p);
        float l  = has_left  ? __ldg(p - 1) : 0.0f;
        float rr = has_right ? __ldg(p + 4) : 0.0f;
        return hmax4(t4, l, rr);
    };

    float4 tcur, tnext, tdump;
    float4 hm_m1, hm_0, hm_p1;

    if (y0 > 0) hm_m1 = load_row(r0 - 1, tdump);
    else        hm_m1 = make_float4(0.f, 0.f, 0.f, 0.f);
    hm_0 = load_row(r0, tcur);

    float acc = 0.0f;

    #pragma unroll
    for (int i = 0; i < RPB; ++i) {
        const int r = r0 + i;
        const int y = y0 + i;

        if (y < Hd - 1) {
            hm_p1 = load_row(r + 1, tnext);
        } else {
            hm_p1 = make_float4(0.f, 0.f, 0.f, 0.f);
            tnext = make_float4(0.f, 0.f, 0.f, 0.f);
        }

        float4 p4 = *reinterpret_cast<const float4*>(pred + (size_t)r * Wd + x4);

        float dil[4];
        dil[0] = fmaxf(hm_m1.x, fmaxf(hm_0.x, hm_p1.x));
        dil[1] = fmaxf(hm_m1.y, fmaxf(hm_0.y, hm_p1.y));
        dil[2] = fmaxf(hm_m1.z, fmaxf(hm_0.z, hm_p1.z));
        dil[3] = fmaxf(hm_m1.w, fmaxf(hm_0.w, hm_p1.w));

        float tv[4] = {tcur.x, tcur.y, tcur.z, tcur.w};
        float xv[4] = {p4.x,   p4.y,   p4.z,   p4.w};

        #pragma unroll
        for (int j = 0; j < 4; ++j) {
            float t = tv[j];
            float x = xv[j];
            float w = (t > 0.5f) ? 20.0f : ((dil[j] > 0.5f) ? 5.0f : 1.0f);
            float a  = fabsf(x);
            float sp = __logf(1.0f + __expf(-a));     // log1p(exp(-|x|)), |x|>=0
            acc = fmaf(w, fmaxf(x, 0.0f) - x * t + sp, acc);
        }

        // roll the row window
        hm_m1 = hm_0;
        hm_0  = hm_p1;
        tcur  = tnext;
    }

    // deterministic block reduction (fixed tree order)
    #pragma unroll
    for (int off = 16; off > 0; off >>= 1)
        acc += __shfl_down_sync(0xffffffffu, acc, off);

    __shared__ float smem[TPB / 32];
    const int lane = threadIdx.x & 31;
    const int wid  = threadIdx.x >> 5;
    if (lane == 0) smem[wid] = acc;
    __syncthreads();
    if (wid == 0) {
        acc = (lane < TPB / 32) ? smem[lane] : 0.0f;
        #pragma unroll
        for (int off = 4; off > 0; off >>= 1)
            acc += __shfl_down_sync(0xffffffffu, acc, off);
        if (lane == 0) g_partial[blockIdx.x] = acc;
    }
}

__global__ __launch_bounds__(256)
void bce_final_kernel(float* __restrict__ out) {
    double s = 0.0;
    for (int i = threadIdx.x; i < NBLK; i += 256)
        s += (double)g_partial[i];

    #pragma unroll
    for (int off = 16; off > 0; off >>= 1)
        s += __shfl_down_sync(0xffffffffu, s, off);

    __shared__ double sm[8];
    const int lane = threadIdx.x & 31;
    const int wid  = threadIdx.x >> 5;
    if (lane == 0) sm[wid] = s;
    __syncthreads();
    if (wid == 0) {
        s = (lane < 8) ? sm[lane] : 0.0;
        #pragma unroll
        for (int off = 4; off > 0; off >>= 1)
            s += __shfl_down_sync(0xffffffffu, s, off);
        if (lane == 0)
            out[0] = (float)(s / (double)((size_t)Bd * Hd * Wd));
    }
}

extern "C" void kernel_launch(void* const* d_in, const int* in_sizes, int n_in,
                              void* d_out, int out_size) {
    const float* pred = (const float*)d_in[0];
    const float* tgt  = (const float*)d_in[1];
    float* out = (float*)d_out;

    bce_partial_kernel<<<NBLK, TPB>>>(pred, tgt);
    bce_final_kernel<<<1, 256>>>(out);
}